// round 3
// baseline (speedup 1.0000x reference)
#include <cuda_runtime.h>

#define NN 50000

// Scratch (no allocations allowed -> __device__ globals)
__device__ __align__(16) float g_deg[NN];
__device__ __align__(16) float g_dinv[NN];
__device__ __align__(16) float g_xw[(size_t)NN * 128];   // x @ W1
__device__ __align__(16) float g_tmp[(size_t)NN * 128];  // aggregated layer-1 / h after tanh
__device__ __align__(16) float g_hw[(size_t)NN * 64];    // h @ W2

// ---------------------------------------------------------------------------
// degree / normalization
// ---------------------------------------------------------------------------
__global__ void deg_init_kernel(int n) {
    int i = blockIdx.x * blockDim.x + threadIdx.x;
    if (i < n) g_deg[i] = 1.0f;  // self loop
}

__global__ void deg_accum_kernel(const int* __restrict__ dst, int E) {
    int i = blockIdx.x * blockDim.x + threadIdx.x;
    if (i < E) atomicAdd(&g_deg[dst[i]], 1.0f);
}

__global__ void dinv_kernel(int n) {
    int i = blockIdx.x * blockDim.x + threadIdx.x;
    if (i < n) {
        float d = g_deg[i];
        g_dinv[i] = (d > 0.0f) ? rsqrtf(d) : 0.0f;
    }
}

// ---------------------------------------------------------------------------
// simple tiled SGEMM: C[M,N] = A[M,K] @ B[K,N], row-major.
// K and N assumed multiples of BK / BN; M ragged (guarded).
// ---------------------------------------------------------------------------
template <int BM, int BN, int BK, int TM, int TN>
__global__ void sgemm_kernel(const float* __restrict__ A,
                             const float* __restrict__ B,
                             float* __restrict__ C,
                             int M, int N, int K) {
    constexpr int THREADS = (BM / TM) * (BN / TN);
    __shared__ float As[BK][BM];
    __shared__ float Bs[BK][BN];

    const int tid = threadIdx.x;
    const int block_row = blockIdx.y * BM;
    const int block_col = blockIdx.x * BN;
    const int tcol = tid % (BN / TN);
    const int trow = tid / (BN / TN);

    float acc[TM][TN];
#pragma unroll
    for (int i = 0; i < TM; i++)
#pragma unroll
        for (int j = 0; j < TN; j++) acc[i][j] = 0.0f;

    for (int k0 = 0; k0 < K; k0 += BK) {
        // load A tile (transpose into As[k][m]), float4 along K
        constexpr int A_VECS = BM * BK / 4;
#pragma unroll
        for (int i = tid; i < A_VECS; i += THREADS) {
            int m = i / (BK / 4);
            int kv = i % (BK / 4);
            float4 v = make_float4(0.f, 0.f, 0.f, 0.f);
            int row = block_row + m;
            if (row < M)
                v = *(const float4*)&A[(size_t)row * K + k0 + kv * 4];
            As[kv * 4 + 0][m] = v.x;
            As[kv * 4 + 1][m] = v.y;
            As[kv * 4 + 2][m] = v.z;
            As[kv * 4 + 3][m] = v.w;
        }
        // load B tile
        constexpr int B_VECS = BK * BN / 4;
#pragma unroll
        for (int i = tid; i < B_VECS; i += THREADS) {
            int k = i / (BN / 4);
            int nv = i % (BN / 4);
            float4 v = *(const float4*)&B[(size_t)(k0 + k) * N + block_col + nv * 4];
            *(float4*)&Bs[k][nv * 4] = v;
        }
        __syncthreads();

#pragma unroll
        for (int k = 0; k < BK; k++) {
            float a[TM], b[TN];
#pragma unroll
            for (int i = 0; i < TM; i++) a[i] = As[k][trow * TM + i];
#pragma unroll
            for (int j = 0; j < TN; j++) b[j] = Bs[k][tcol * TN + j];
#pragma unroll
            for (int i = 0; i < TM; i++)
#pragma unroll
                for (int j = 0; j < TN; j++) acc[i][j] += a[i] * b[j];
        }
        __syncthreads();
    }

#pragma unroll
    for (int i = 0; i < TM; i++) {
        int row = block_row + trow * TM + i;
        if (row >= M) continue;
#pragma unroll
        for (int j = 0; j < TN; j += 4) {
            float4 v = make_float4(acc[i][j], acc[i][j + 1], acc[i][j + 2], acc[i][j + 3]);
            *(float4*)&C[(size_t)row * N + block_col + tcol * TN + j] = v;
        }
    }
}

// ---------------------------------------------------------------------------
// layer-1 aggregation
// ---------------------------------------------------------------------------
// init tmp with self-loop contribution: tmp[i,:] = xw[i,:] * dinv[i]^2
__global__ void self_init1_kernel(int n) {
    int idx = blockIdx.x * blockDim.x + threadIdx.x;  // over n*32 float4s
    if (idx >= n * 32) return;
    int node = idx >> 5;
    float s = g_dinv[node];
    s = s * s;
    float4 v = ((const float4*)g_xw)[idx];
    v.x *= s; v.y *= s; v.z *= s; v.w *= s;
    ((float4*)g_tmp)[idx] = v;
}

// one warp per edge, 128 cols = 32 lanes x float4, vector reduction to tmp[dst]
__global__ void scatter1_kernel(const int* __restrict__ src,
                                const int* __restrict__ dst, int E) {
    int gtid = blockIdx.x * blockDim.x + threadIdx.x;
    int warp = gtid >> 5;
    int lane = gtid & 31;
    if (warp >= E) return;
    int s = src[warp];
    int d = dst[warp];
    float norm = g_dinv[s] * g_dinv[d];
    float4 v = *(const float4*)&g_xw[(size_t)s * 128 + lane * 4];
    v.x *= norm; v.y *= norm; v.z *= norm; v.w *= norm;
    atomicAdd((float4*)&g_tmp[(size_t)d * 128 + lane * 4], v);
}

// h = tanh(tmp + b1), in place
__global__ void tanh_bias_kernel(const float* __restrict__ b1, int n) {
    int idx = blockIdx.x * blockDim.x + threadIdx.x;  // over n*32 float4s
    if (idx >= n * 32) return;
    int c4 = idx & 31;
    float4 bb = ((const float4*)b1)[c4];
    float4 v = ((float4*)g_tmp)[idx];
    v.x = tanhf(v.x + bb.x);
    v.y = tanhf(v.y + bb.y);
    v.z = tanhf(v.z + bb.z);
    v.w = tanhf(v.w + bb.w);
    ((float4*)g_tmp)[idx] = v;
}

// ---------------------------------------------------------------------------
// layer-2 aggregation (64 cols)
// ---------------------------------------------------------------------------
// out[i,:] = hw[i,:] * dinv[i]^2 + b2   (self loop + bias; also initializes out)
__global__ void self_init2_kernel(const float* __restrict__ b2,
                                  float* __restrict__ out, int n) {
    int idx = blockIdx.x * blockDim.x + threadIdx.x;  // over n*16 float4s
    if (idx >= n * 16) return;
    int node = idx >> 4;
    int c4 = idx & 15;
    float s = g_dinv[node];
    s = s * s;
    float4 v = ((const float4*)g_hw)[idx];
    float4 bb = ((const float4*)b2)[c4];
    v.x = v.x * s + bb.x;
    v.y = v.y * s + bb.y;
    v.z = v.z * s + bb.z;
    v.w = v.w * s + bb.w;
    ((float4*)out)[idx] = v;
}

// one warp per edge, 64 cols = 32 lanes x float2
__global__ void scatter2_kernel(const int* __restrict__ src,
                                const int* __restrict__ dst,
                                float* __restrict__ out, int E) {
    int gtid = blockIdx.x * blockDim.x + threadIdx.x;
    int warp = gtid >> 5;
    int lane = gtid & 31;
    if (warp >= E) return;
    int s = src[warp];
    int d = dst[warp];
    float norm = g_dinv[s] * g_dinv[d];
    float2 v = *(const float2*)&g_hw[(size_t)s * 64 + lane * 2];
    v.x *= norm; v.y *= norm;
    atomicAdd((float2*)&out[(size_t)d * 64 + lane * 2], v);
}

// ---------------------------------------------------------------------------
extern "C" void kernel_launch(void* const* d_in, const int* in_sizes, int n_in,
                              void* d_out, int out_size) {
    const float* x   = (const float*)d_in[0];
    const int* ei    = (const int*)d_in[1];   // int32 (jax x64 disabled)
    const float* W1  = (const float*)d_in[2];
    const float* b1  = (const float*)d_in[3];
    const float* W2  = (const float*)d_in[4];
    const float* b2  = (const float*)d_in[5];
    float* out       = (float*)d_out;

    const int E = in_sizes[1] / 2;
    const int* src = ei;
    const int* dst = ei + E;

    float *xw_p, *tmp_p, *hw_p;
    cudaGetSymbolAddress((void**)&xw_p, g_xw);
    cudaGetSymbolAddress((void**)&tmp_p, g_tmp);
    cudaGetSymbolAddress((void**)&hw_p, g_hw);

    const int T = 256;

    // normalization
    deg_init_kernel<<<(NN + T - 1) / T, T>>>(NN);
    deg_accum_kernel<<<(E + T - 1) / T, T>>>(dst, E);
    dinv_kernel<<<(NN + T - 1) / T, T>>>(NN);

    // layer 1: xw = x @ W1   (M=NN, K=256, N=128)
    {
        dim3 grid(1, (NN + 127) / 128);
        sgemm_kernel<128, 128, 16, 8, 8><<<grid, 256>>>(x, W1, xw_p, NN, 128, 256);
    }
    self_init1_kernel<<<(NN * 32 + T - 1) / T, T>>>(NN);
    scatter1_kernel<<<(int)(((size_t)E * 32 + T - 1) / T), T>>>(src, dst, E);
    tanh_bias_kernel<<<(NN * 32 + T - 1) / T, T>>>(b1, NN);

    // layer 2: hw = h @ W2   (M=NN, K=128, N=64)
    {
        dim3 grid(1, (NN + 127) / 128);
        sgemm_kernel<128, 64, 16, 8, 4><<<grid, 256>>>(tmp_p, W2, hw_p, NN, 64, 128);
    }
    self_init2_kernel<<<(NN * 16 + T - 1) / T, T>>>(b2, out, NN);
    scatter2_kernel<<<(int)(((size_t)E * 32 + T - 1) / T), T>>>(src, dst, out, E);
}

// round 5
// speedup vs baseline: 1.3137x; 1.3137x over previous
#include <cuda_runtime.h>
#include <cstdint>

#define NN 50000

// Scratch (no allocations allowed -> __device__ globals)
__device__ __align__(16) float g_deg[NN];
__device__ __align__(16) float g_dinv[NN];
__device__ __align__(16) float g_xw[(size_t)NN * 128];   // x @ W1
__device__ __align__(16) float g_tmp[(size_t)NN * 128];  // xw*dinv^2, then scatter-accumulated (pre-activation)
__device__ __align__(16) float g_hw[(size_t)NN * 64];    // h @ W2

// ---------------------------------------------------------------------------
// degree / normalization
// ---------------------------------------------------------------------------
__global__ void deg_init_kernel(int n) {
    int i = blockIdx.x * blockDim.x + threadIdx.x;
    if (i < n) g_deg[i] = 1.0f;  // self loop
}

__global__ void deg_accum_kernel(const int* __restrict__ dst, int E) {
    int i = blockIdx.x * blockDim.x + threadIdx.x;
    if (i < E) atomicAdd(&g_deg[dst[i]], 1.0f);
}

__global__ void dinv_kernel(int n) {
    int i = blockIdx.x * blockDim.x + threadIdx.x;
    if (i < n) {
        float d = g_deg[i];
        g_dinv[i] = (d > 0.0f) ? rsqrtf(d) : 0.0f;
    }
}

// ---------------------------------------------------------------------------
// TF32 tensor-core GEMM: C[M,N] = op(A)[M,K] @ B[K,N], row-major.
// MODE 1: C = A@B (g_xw), C2 = C * dinv[row]^2 (g_tmp)
// MODE 2: A' = tanh(A + bias_in) applied at load; C = A'@B (g_hw),
//         C2 = C * dinv[row]^2 + bias_out (final out)
// ---------------------------------------------------------------------------
__device__ __forceinline__ unsigned int f2tf32(float f) {
    unsigned int r;
    asm("cvt.rna.tf32.f32 %0, %1;" : "=r"(r) : "f"(f));
    return r;
}

template <int BM, int BN, int BK, int WM, int WN, int MODE>
__global__ void __launch_bounds__((BM / WM) * (BN / WN) * 32)
mma_gemm_kernel(const float* __restrict__ A, const float* __restrict__ B,
                const float* __restrict__ bias_in, const float* __restrict__ bias_out,
                float* __restrict__ C, float* __restrict__ C2,
                int M, int N, int K) {
    constexpr int WARPS_M = BM / WM;
    constexpr int WARPS_N = BN / WN;
    constexpr int THREADS = WARPS_M * WARPS_N * 32;
    constexpr int MI = WM / 16;
    constexpr int NI = WN / 8;

    __shared__ float As[BM][BK + 4];
    __shared__ float Bs[BK][BN + 8];

    const int tid = threadIdx.x;
    const int warp = tid >> 5;
    const int lane = tid & 31;
    const int g = lane >> 2;   // group id
    const int t = lane & 3;    // thread in group
    const int warp_m = warp % WARPS_M;
    const int warp_n = warp / WARPS_M;
    const int block_row = blockIdx.y * BM;

    float acc[MI][NI][4];
#pragma unroll
    for (int mi = 0; mi < MI; mi++)
#pragma unroll
        for (int ni = 0; ni < NI; ni++)
#pragma unroll
            for (int j = 0; j < 4; j++) acc[mi][ni][j] = 0.0f;

    for (int k0 = 0; k0 < K; k0 += BK) {
        // ---- load A tile [BM x BK] ----
        constexpr int AV = BM * BK / 4;
#pragma unroll
        for (int i = tid; i < AV; i += THREADS) {
            int m = i / (BK / 4);
            int kv = i % (BK / 4);
            int row = block_row + m;
            float4 v = make_float4(0.f, 0.f, 0.f, 0.f);
            if (row < M) v = *(const float4*)&A[(size_t)row * K + k0 + kv * 4];
            if (MODE == 2) {
                int kb = k0 + kv * 4;
                v.x = tanhf(v.x + bias_in[kb + 0]);
                v.y = tanhf(v.y + bias_in[kb + 1]);
                v.z = tanhf(v.z + bias_in[kb + 2]);
                v.w = tanhf(v.w + bias_in[kb + 3]);
            }
            *(float4*)&As[m][kv * 4] = v;
        }
        // ---- load B tile [BK x BN] ----
        constexpr int BV = BK * BN / 4;
#pragma unroll
        for (int i = tid; i < BV; i += THREADS) {
            int k = i / (BN / 4);
            int nv = i % (BN / 4);
            float4 v = *(const float4*)&B[(size_t)(k0 + k) * N + nv * 4];
            *(float4*)&Bs[k][nv * 4] = v;
        }
        __syncthreads();

#pragma unroll
        for (int kk = 0; kk < BK / 8; kk++) {
            unsigned int af[MI][4];
#pragma unroll
            for (int mi = 0; mi < MI; mi++) {
                int r = warp_m * WM + mi * 16;
                af[mi][0] = f2tf32(As[r + g][kk * 8 + t]);
                af[mi][1] = f2tf32(As[r + g + 8][kk * 8 + t]);
                af[mi][2] = f2tf32(As[r + g][kk * 8 + t + 4]);
                af[mi][3] = f2tf32(As[r + g + 8][kk * 8 + t + 4]);
            }
            unsigned int bf[NI][2];
#pragma unroll
            for (int ni = 0; ni < NI; ni++) {
                int c = warp_n * WN + ni * 8 + g;
                bf[ni][0] = f2tf32(Bs[kk * 8 + t][c]);
                bf[ni][1] = f2tf32(Bs[kk * 8 + t + 4][c]);
            }
#pragma unroll
            for (int mi = 0; mi < MI; mi++)
#pragma unroll
                for (int ni = 0; ni < NI; ni++) {
                    asm volatile(
                        "mma.sync.aligned.m16n8k8.row.col.f32.tf32.tf32.f32 "
                        "{%0,%1,%2,%3}, {%4,%5,%6,%7}, {%8,%9}, {%0,%1,%2,%3};"
                        : "+f"(acc[mi][ni][0]), "+f"(acc[mi][ni][1]),
                          "+f"(acc[mi][ni][2]), "+f"(acc[mi][ni][3])
                        : "r"(af[mi][0]), "r"(af[mi][1]), "r"(af[mi][2]), "r"(af[mi][3]),
                          "r"(bf[ni][0]), "r"(bf[ni][1]));
                }
        }
        __syncthreads();
    }

    // ---- epilogue ----
#pragma unroll
    for (int mi = 0; mi < MI; mi++) {
        int r0 = block_row + warp_m * WM + mi * 16 + g;
        int r1 = r0 + 8;
#pragma unroll
        for (int ni = 0; ni < NI; ni++) {
            int c = warp_n * WN + ni * 8 + t * 2;
            if (r0 < M) {
                float2 v = make_float2(acc[mi][ni][0], acc[mi][ni][1]);
                *(float2*)&C[(size_t)r0 * N + c] = v;
                float s = g_dinv[r0]; s = s * s;
                float2 w;
                if (MODE == 1) { w = make_float2(v.x * s, v.y * s); }
                else { w = make_float2(v.x * s + bias_out[c], v.y * s + bias_out[c + 1]); }
                *(float2*)&C2[(size_t)r0 * N + c] = w;
            }
            if (r1 < M) {
                float2 v = make_float2(acc[mi][ni][2], acc[mi][ni][3]);
                *(float2*)&C[(size_t)r1 * N + c] = v;
                float s = g_dinv[r1]; s = s * s;
                float2 w;
                if (MODE == 1) { w = make_float2(v.x * s, v.y * s); }
                else { w = make_float2(v.x * s + bias_out[c], v.y * s + bias_out[c + 1]); }
                *(float2*)&C2[(size_t)r1 * N + c] = w;
            }
        }
    }
}

// ---------------------------------------------------------------------------
// edge scatter kernels
// ---------------------------------------------------------------------------
// one warp per edge, 128 cols = 32 lanes x float4, vector reduction to tmp[dst]
__global__ void scatter1_kernel(const int* __restrict__ src,
                                const int* __restrict__ dst, int E) {
    int gtid = blockIdx.x * blockDim.x + threadIdx.x;
    int warp = gtid >> 5;
    int lane = gtid & 31;
    if (warp >= E) return;
    int s = src[warp];
    int d = dst[warp];
    float norm = g_dinv[s] * g_dinv[d];
    float4 v = *(const float4*)&g_xw[(size_t)s * 128 + lane * 4];
    v.x *= norm; v.y *= norm; v.z *= norm; v.w *= norm;
    atomicAdd((float4*)&g_tmp[(size_t)d * 128 + lane * 4], v);
}

// one warp per edge, 64 cols = 32 lanes x float2
__global__ void scatter2_kernel(const int* __restrict__ src,
                                const int* __restrict__ dst,
                                float* __restrict__ out, int E) {
    int gtid = blockIdx.x * blockDim.x + threadIdx.x;
    int warp = gtid >> 5;
    int lane = gtid & 31;
    if (warp >= E) return;
    int s = src[warp];
    int d = dst[warp];
    float norm = g_dinv[s] * g_dinv[d];
    float2 v = *(const float2*)&g_hw[(size_t)s * 64 + lane * 2];
    v.x *= norm; v.y *= norm;
    atomicAdd((float2*)&out[(size_t)d * 64 + lane * 2], v);
}

// ---------------------------------------------------------------------------
extern "C" void kernel_launch(void* const* d_in, const int* in_sizes, int n_in,
                              void* d_out, int out_size) {
    const float* x   = (const float*)d_in[0];
    const int* ei    = (const int*)d_in[1];   // int32 (jax x64 disabled)
    const float* W1  = (const float*)d_in[2];
    const float* b1  = (const float*)d_in[3];
    const float* W2  = (const float*)d_in[4];
    const float* b2  = (const float*)d_in[5];
    float* out       = (float*)d_out;

    const int E = in_sizes[1] / 2;
    const int* src = ei;
    const int* dst = ei + E;

    float *xw_p, *tmp_p, *hw_p;
    cudaGetSymbolAddress((void**)&xw_p, g_xw);
    cudaGetSymbolAddress((void**)&tmp_p, g_tmp);
    cudaGetSymbolAddress((void**)&hw_p, g_hw);

    const int T = 256;

    // normalization (dinv needed before gemm1 epilogue)
    deg_init_kernel<<<(NN + T - 1) / T, T>>>(NN);
    deg_accum_kernel<<<(E + T - 1) / T, T>>>(dst, E);
    dinv_kernel<<<(NN + T - 1) / T, T>>>(NN);

    // layer 1: xw = x @ W1 (tf32 MMA); tmp = xw * dinv^2 fused
    {
        dim3 grid(1, (NN + 127) / 128);
        mma_gemm_kernel<128, 128, 32, 64, 32, 1><<<grid, 256>>>(
            x, W1, nullptr, nullptr, xw_p, tmp_p, NN, 128, 256);
    }
    scatter1_kernel<<<(int)(((size_t)E * 32 + T - 1) / T), T>>>(src, dst, E);

    // layer 2: h = tanh(tmp + b1) fused into A-load; hw = h @ W2;
    //          out = hw * dinv^2 + b2 fused
    {
        dim3 grid(1, (NN + 127) / 128);
        mma_gemm_kernel<128, 64, 32, 32, 32, 2><<<grid, 256>>>(
            tmp_p, W2, b1, b2, hw_p, out, NN, 64, 128);
    }
    scatter2_kernel<<<(int)(((size_t)E * 32 + T - 1) / T), T>>>(src, dst, out, E);
}

// round 7
// speedup vs baseline: 1.9397x; 1.4765x over previous
#include <cuda_runtime.h>
#include <cstdint>

#define NN 50000
#define EMAX 800000

// Scratch (no allocations allowed -> __device__ globals)
__device__ __align__(16) int   g_degi[NN];
__device__ __align__(16) int   g_ptr[NN + 1];
__device__ __align__(16) int   g_cursor[NN];
__device__ __align__(16) int   g_esrc[EMAX];
__device__ __align__(16) float g_dinv[NN];
__device__ __align__(16) float g_xw[(size_t)NN * 128];   // x @ W1
__device__ __align__(16) float g_tmp[(size_t)NN * 128];  // h = tanh(aggregated + b1)
__device__ __align__(16) float g_hw[(size_t)NN * 64];    // h @ W2

// ---------------------------------------------------------------------------
// CSR build + normalization
// ---------------------------------------------------------------------------
__global__ void zero_kernel(int n) {
    int i = blockIdx.x * blockDim.x + threadIdx.x;
    if (i < n) { g_degi[i] = 0; g_cursor[i] = 0; }
}

__global__ void hist_kernel(const int* __restrict__ dst, int E) {
    int i = blockIdx.x * blockDim.x + threadIdx.x;
    if (i < E) atomicAdd(&g_degi[dst[i]], 1);
}

// single-block exclusive scan of g_degi -> g_ptr  (g_ptr[NN] = E)
__global__ void scan_kernel() {
    __shared__ int partial[1024];
    const int CH = (NN + 1023) / 1024;
    int t = threadIdx.x;
    int base = t * CH;
    int sum = 0;
    for (int i = 0; i < CH; i++) {
        int idx = base + i;
        if (idx < NN) sum += g_degi[idx];
    }
    partial[t] = sum;
    __syncthreads();
    for (int off = 1; off < 1024; off <<= 1) {
        int v = (t >= off) ? partial[t - off] : 0;
        __syncthreads();
        partial[t] += v;
        __syncthreads();
    }
    int run = (t == 0) ? 0 : partial[t - 1];
    for (int i = 0; i < CH; i++) {
        int idx = base + i;
        if (idx < NN) { g_ptr[idx] = run; run += g_degi[idx]; }
    }
    if (t == 1023) g_ptr[NN] = run;
}

__global__ void dinv_kernel(int n) {
    int i = blockIdx.x * blockDim.x + threadIdx.x;
    if (i < n) g_dinv[i] = rsqrtf((float)(g_degi[i] + 1));  // +1 = self loop
}

__global__ void fill_kernel(const int* __restrict__ src,
                            const int* __restrict__ dst, int E) {
    int i = blockIdx.x * blockDim.x + threadIdx.x;
    if (i >= E) return;
    int d = dst[i];
    int pos = g_ptr[d] + atomicAdd(&g_cursor[d], 1);
    if (pos < EMAX) g_esrc[pos] = src[i];
}

// ---------------------------------------------------------------------------
// TF32 tensor-core GEMM, 2-stage cp.async pipeline.
// C[M,N] = A[M,K] @ B[K,N], row-major, N/K multiples of BN/BK, M ragged.
// ---------------------------------------------------------------------------
__device__ __forceinline__ unsigned int f2tf32(float f) {
    unsigned int r;
    asm("cvt.rna.tf32.f32 %0, %1;" : "=r"(r) : "f"(f));
    return r;
}

__device__ __forceinline__ void cp_async16(void* smem, const void* gmem, int pred_sz) {
    unsigned int sa = (unsigned int)__cvta_generic_to_shared(smem);
    asm volatile("cp.async.cg.shared.global [%0], [%1], 16, %2;\n"
                 :: "r"(sa), "l"(gmem), "r"(pred_sz));
}

template <int BM, int BN, int BK, int WM, int WN>
__global__ void __launch_bounds__((BM / WM) * (BN / WN) * 32)
mma_gemm_kernel(const float* __restrict__ A, const float* __restrict__ B,
                float* __restrict__ C, int M, int N, int K) {
    constexpr int WARPS_M = BM / WM;
    constexpr int WARPS_N = BN / WN;
    constexpr int THREADS = WARPS_M * WARPS_N * 32;
    constexpr int MI = WM / 16;
    constexpr int NI = WN / 8;
    constexpr int APAD = 4, BPAD = 8;

    __shared__ float As[2][BM][BK + APAD];
    __shared__ float Bs[2][BK][BN + BPAD];

    const int tid = threadIdx.x;
    const int warp = tid >> 5;
    const int lane = tid & 31;
    const int g = lane >> 2;
    const int t = lane & 3;
    const int warp_m = warp % WARPS_M;
    const int warp_n = warp / WARPS_M;
    const int block_row = blockIdx.y * BM;

    float acc[MI][NI][4];
#pragma unroll
    for (int mi = 0; mi < MI; mi++)
#pragma unroll
        for (int ni = 0; ni < NI; ni++)
#pragma unroll
            for (int j = 0; j < 4; j++) acc[mi][ni][j] = 0.0f;

    const int KT = K / BK;

    // tile loader via cp.async (counts are in float4 units!)
    auto load_tiles = [&](int kt, int buf) {
        int k0 = kt * BK;
        constexpr int AV = BM * BK / 4;
#pragma unroll
        for (int i = tid; i < AV; i += THREADS) {
            int m = i / (BK / 4);
            int kv = i % (BK / 4);
            int row = block_row + m;
            int rc = row < M ? row : (M - 1);
            cp_async16(&As[buf][m][kv * 4], &A[(size_t)rc * K + k0 + kv * 4],
                       row < M ? 16 : 0);
        }
        constexpr int BV = BK * BN / 4;
#pragma unroll
        for (int i = tid; i < BV; i += THREADS) {
            int k = i / (BN / 4);
            int nv = i % (BN / 4);
            cp_async16(&Bs[buf][k][nv * 4], &B[(size_t)(k0 + k) * N + nv * 4], 16);
        }
    };

    load_tiles(0, 0);
    asm volatile("cp.async.commit_group;\n");

    for (int kt = 0; kt < KT; kt++) {
        asm volatile("cp.async.wait_group 0;\n");
        __syncthreads();
        if (kt + 1 < KT) {
            load_tiles(kt + 1, (kt + 1) & 1);
            asm volatile("cp.async.commit_group;\n");
        }
        int buf = kt & 1;
#pragma unroll
        for (int kk = 0; kk < BK / 8; kk++) {
            unsigned int af[MI][4];
#pragma unroll
            for (int mi = 0; mi < MI; mi++) {
                int r = warp_m * WM + mi * 16;
                af[mi][0] = f2tf32(As[buf][r + g][kk * 8 + t]);
                af[mi][1] = f2tf32(As[buf][r + g + 8][kk * 8 + t]);
                af[mi][2] = f2tf32(As[buf][r + g][kk * 8 + t + 4]);
                af[mi][3] = f2tf32(As[buf][r + g + 8][kk * 8 + t + 4]);
            }
            unsigned int bf[NI][2];
#pragma unroll
            for (int ni = 0; ni < NI; ni++) {
                int c = warp_n * WN + ni * 8 + g;
                bf[ni][0] = f2tf32(Bs[buf][kk * 8 + t][c]);
                bf[ni][1] = f2tf32(Bs[buf][kk * 8 + t + 4][c]);
            }
#pragma unroll
            for (int mi = 0; mi < MI; mi++)
#pragma unroll
                for (int ni = 0; ni < NI; ni++) {
                    asm volatile(
                        "mma.sync.aligned.m16n8k8.row.col.f32.tf32.tf32.f32 "
                        "{%0,%1,%2,%3}, {%4,%5,%6,%7}, {%8,%9}, {%0,%1,%2,%3};"
                        : "+f"(acc[mi][ni][0]), "+f"(acc[mi][ni][1]),
                          "+f"(acc[mi][ni][2]), "+f"(acc[mi][ni][3])
                        : "r"(af[mi][0]), "r"(af[mi][1]), "r"(af[mi][2]), "r"(af[mi][3]),
                          "r"(bf[ni][0]), "r"(bf[ni][1]));
                }
        }
        __syncthreads();
    }

    // ---- epilogue: plain store ----
#pragma unroll
    for (int mi = 0; mi < MI; mi++) {
        int r0 = block_row + warp_m * WM + mi * 16 + g;
        int r1 = r0 + 8;
#pragma unroll
        for (int ni = 0; ni < NI; ni++) {
            int c = warp_n * WN + ni * 8 + t * 2;
            if (r0 < M)
                *(float2*)&C[(size_t)r0 * N + c] = make_float2(acc[mi][ni][0], acc[mi][ni][1]);
            if (r1 < M)
                *(float2*)&C[(size_t)r1 * N + c] = make_float2(acc[mi][ni][2], acc[mi][ni][3]);
        }
    }
}

// ---------------------------------------------------------------------------
// CSR gather aggregation (no atomics): one warp per node.
// ---------------------------------------------------------------------------
// layer 1: tmp[d,:] = tanh( dinv[d]*sum_s xw[s,:]*dinv[s] + xw[d,:]*dinv[d]^2 + b1 )
__global__ void gather1_kernel(const float* __restrict__ b1) {
    int node = blockIdx.x * (blockDim.x >> 5) + (threadIdx.x >> 5);
    int lane = threadIdx.x & 31;
    if (node >= NN) return;
    int e = g_ptr[node], end = g_ptr[node + 1];
    float dd = g_dinv[node];
    float4 acc = make_float4(0.f, 0.f, 0.f, 0.f);
    for (; e + 4 <= end; e += 4) {
        int s0 = g_esrc[e], s1 = g_esrc[e + 1], s2 = g_esrc[e + 2], s3 = g_esrc[e + 3];
        float w0 = g_dinv[s0], w1 = g_dinv[s1], w2 = g_dinv[s2], w3 = g_dinv[s3];
        float4 v0 = *(const float4*)&g_xw[(size_t)s0 * 128 + lane * 4];
        float4 v1 = *(const float4*)&g_xw[(size_t)s1 * 128 + lane * 4];
        float4 v2 = *(const float4*)&g_xw[(size_t)s2 * 128 + lane * 4];
        float4 v3 = *(const float4*)&g_xw[(size_t)s3 * 128 + lane * 4];
        acc.x += v0.x * w0 + v1.x * w1 + v2.x * w2 + v3.x * w3;
        acc.y += v0.y * w0 + v1.y * w1 + v2.y * w2 + v3.y * w3;
        acc.z += v0.z * w0 + v1.z * w1 + v2.z * w2 + v3.z * w3;
        acc.w += v0.w * w0 + v1.w * w1 + v2.w * w2 + v3.w * w3;
    }
    for (; e < end; e++) {
        int s = g_esrc[e];
        float w = g_dinv[s];
        float4 v = *(const float4*)&g_xw[(size_t)s * 128 + lane * 4];
        acc.x += v.x * w; acc.y += v.y * w; acc.z += v.z * w; acc.w += v.w * w;
    }
    float4 self = *(const float4*)&g_xw[(size_t)node * 128 + lane * 4];
    float4 bb = ((const float4*)b1)[lane];
    float dd2 = dd * dd;
    float4 o;
    o.x = tanhf(acc.x * dd + self.x * dd2 + bb.x);
    o.y = tanhf(acc.y * dd + self.y * dd2 + bb.y);
    o.z = tanhf(acc.z * dd + self.z * dd2 + bb.z);
    o.w = tanhf(acc.w * dd + self.w * dd2 + bb.w);
    *(float4*)&g_tmp[(size_t)node * 128 + lane * 4] = o;
}

// layer 2: out[d,:] = dinv[d]*sum_s hw[s,:]*dinv[s] + hw[d,:]*dinv[d]^2 + b2
__global__ void gather2_kernel(const float* __restrict__ b2, float* __restrict__ out) {
    int node = blockIdx.x * (blockDim.x >> 5) + (threadIdx.x >> 5);
    int lane = threadIdx.x & 31;
    if (node >= NN) return;
    int e = g_ptr[node], end = g_ptr[node + 1];
    float dd = g_dinv[node];
    float2 acc = make_float2(0.f, 0.f);
    for (; e + 4 <= end; e += 4) {
        int s0 = g_esrc[e], s1 = g_esrc[e + 1], s2 = g_esrc[e + 2], s3 = g_esrc[e + 3];
        float w0 = g_dinv[s0], w1 = g_dinv[s1], w2 = g_dinv[s2], w3 = g_dinv[s3];
        float2 v0 = *(const float2*)&g_hw[(size_t)s0 * 64 + lane * 2];
        float2 v1 = *(const float2*)&g_hw[(size_t)s1 * 64 + lane * 2];
        float2 v2 = *(const float2*)&g_hw[(size_t)s2 * 64 + lane * 2];
        float2 v3 = *(const float2*)&g_hw[(size_t)s3 * 64 + lane * 2];
        acc.x += v0.x * w0 + v1.x * w1 + v2.x * w2 + v3.x * w3;
        acc.y += v0.y * w0 + v1.y * w1 + v2.y * w2 + v3.y * w3;
    }
    for (; e < end; e++) {
        int s = g_esrc[e];
        float w = g_dinv[s];
        float2 v = *(const float2*)&g_hw[(size_t)s * 64 + lane * 2];
        acc.x += v.x * w; acc.y += v.y * w;
    }
    float2 self = *(const float2*)&g_hw[(size_t)node * 64 + lane * 2];
    float2 bb = ((const float2*)b2)[lane];
    float dd2 = dd * dd;
    float2 o;
    o.x = acc.x * dd + self.x * dd2 + bb.x;
    o.y = acc.y * dd + self.y * dd2 + bb.y;
    *(float2*)&out[(size_t)node * 64 + lane * 2] = o;
}

// ---------------------------------------------------------------------------
extern "C" void kernel_launch(void* const* d_in, const int* in_sizes, int n_in,
                              void* d_out, int out_size) {
    const float* x   = (const float*)d_in[0];
    const int* ei    = (const int*)d_in[1];   // int32 (jax x64 disabled)
    const float* W1  = (const float*)d_in[2];
    const float* b1  = (const float*)d_in[3];
    const float* W2  = (const float*)d_in[4];
    const float* b2  = (const float*)d_in[5];
    float* out       = (float*)d_out;

    const int E = in_sizes[1] / 2;
    const int* src = ei;
    const int* dst = ei + E;

    float *xw_p, *tmp_p, *hw_p;
    cudaGetSymbolAddress((void**)&xw_p, g_xw);
    cudaGetSymbolAddress((void**)&tmp_p, g_tmp);
    cudaGetSymbolAddress((void**)&hw_p, g_hw);

    const int T = 256;

    // CSR + normalization
    zero_kernel<<<(NN + T - 1) / T, T>>>(NN);
    hist_kernel<<<(E + T - 1) / T, T>>>(dst, E);
    scan_kernel<<<1, 1024>>>();
    dinv_kernel<<<(NN + T - 1) / T, T>>>(NN);
    fill_kernel<<<(E + T - 1) / T, T>>>(src, dst, E);

    // layer 1: xw = x @ W1 (tf32 MMA, pipelined)
    {
        dim3 grid(1, (NN + 63) / 64);
        mma_gemm_kernel<64, 128, 32, 32, 32><<<grid, 256>>>(x, W1, xw_p, NN, 128, 256);
    }
    gather1_kernel<<<(NN + 7) / 8, 256>>>(b1);

    // layer 2: hw = h @ W2
    {
        dim3 grid(1, (NN + 63) / 64);
        mma_gemm_kernel<64, 64, 32, 32, 16><<<grid, 256>>>(tmp_p, W2, hw_p, NN, 64, 128);
    }
    gather2_kernel<<<(NN + 7) / 8, 256>>>(b2, out);
}